// round 3
// baseline (speedup 1.0000x reference)
#include <cuda_runtime.h>
#include <cstdint>

// ----------------------------------------------------------------------------
// Problem constants (fixed shapes per reference)
//   N=50000, K=16 neighbors, IN=128, T2V=64, F=IN+T2V=192, H=128
// ----------------------------------------------------------------------------
#define KNBR 16
#define INF  128
#define T2VD 64
#define FD   192
#define HD   128
#define NMAX 50176   // 128 * 392, >= 50000

// Scratch (static device globals — no allocation)
__device__ float g_M[INF * FD];        // 128 x 192 :  (Wq1 @ Wk^T) / sqrt(H)
__device__ float g_c[FD];              // 192       :  (qc  @ Wk^T) / sqrt(H)
__device__ float g_Wvo[FD * HD];       // 192 x 128 :  Wv @ Wo
__device__ float g_A[(size_t)NMAX * FD];   // A rows  (score projections)
__device__ float g_H[(size_t)NMAX * FD];   // HAGG rows

// ----------------------------------------------------------------------------
// prep: build M, c, Wvo from the weight matrices.
// grid = 192 blocks (one per f in 0..191), 128 threads.
// ----------------------------------------------------------------------------
__global__ void prep_kernel(const float* __restrict__ Wq, const float* __restrict__ Wk,
                            const float* __restrict__ Wv, const float* __restrict__ Wo,
                            const float* __restrict__ w0, const float* __restrict__ b0,
                            const float* __restrict__ Wt, const float* __restrict__ Bt)
{
    const int f = blockIdx.x;   // 0..191
    const int t = threadIdx.x;  // 0..127
    __shared__ float wkrow[HD];
    __shared__ float wvrow[HD];
    __shared__ float tev[T2VD];
    __shared__ float red[HD];

    wkrow[t] = Wk[f * HD + t];
    wvrow[t] = Wv[f * HD + t];
    if (t < T2VD) {
        tev[t] = (t == 0) ? b0[0] : sinf(Bt[t - 1]);   // time2vec(0)
    }
    __syncthreads();

    const float scale = 0.08838834764831845f;  // 1/sqrt(128)

    // M[t, f] = scale * sum_h Wq[t,h] * Wk[f,h]       (t < 128 input feats)
    float m = 0.f;
    #pragma unroll 4
    for (int h = 0; h < HD; h++) m = fmaf(Wq[t * HD + h], wkrow[h], m);
    g_M[t * FD + f] = m * scale;

    // Wvo[f, t] = sum_h Wv[f,h] * Wo[h,t]
    float wv = 0.f;
    #pragma unroll 4
    for (int h = 0; h < HD; h++) wv = fmaf(wvrow[h], Wo[h * HD + t], wv);
    g_Wvo[f * HD + t] = wv;

    // qc[t] = sum_j tev[j] * Wq[(128+j), t] ; then c[f] = scale * sum_h qc[h]*Wk[f,h]
    float qc = 0.f;
    #pragma unroll 4
    for (int j = 0; j < T2VD; j++) qc = fmaf(tev[j], Wq[(INF + j) * HD + t], qc);
    red[t] = qc * wkrow[t];
    __syncthreads();
    for (int s = 64; s > 0; s >>= 1) {
        if (t < s) red[t] += red[t + s];
        __syncthreads();
    }
    if (t == 0) g_c[f] = red[0] * scale;
}

// ----------------------------------------------------------------------------
// Generic SGEMM:  C[n,j] = act( sum_k A[n,k]*B[k,j] + bias[j] )
// BM=128, BN=64, BK=32. 256 threads (16x16), 8x4 microtile per thread.
// Rows clamped on load (safe tail), stores guarded.
// ----------------------------------------------------------------------------
#define BM 128
#define BN 64
#define BKT 32
#define ASTRIDE 136   // 128 + 8 pad

__global__ __launch_bounds__(256, 3)
void sgemm_kernel(const float* __restrict__ A, const float* __restrict__ Bm,
                  const float* __restrict__ bias, float* __restrict__ C,
                  int Nrows, int Kd, int Jd, int do_relu)
{
    __shared__ float As[BKT * ASTRIDE];
    __shared__ float Bs[BKT * BN];

    const int t    = threadIdx.x;
    const int trow = t >> 4;   // 0..15
    const int tcol = t & 15;   // 0..15
    const int row0 = blockIdx.y * BM;
    const int j0   = blockIdx.x * BN;

    float acc[8][4];
    #pragma unroll
    for (int i = 0; i < 8; i++)
        #pragma unroll
        for (int j = 0; j < 4; j++) acc[i][j] = 0.f;

    for (int k0 = 0; k0 < Kd; k0 += BKT) {
        // --- load A tile (128 x 32): thread -> row m=t/2, half of the row ---
        {
            const int m    = t >> 1;
            const int half = (t & 1);
            int r = row0 + m;
            if (r >= Nrows) r = Nrows - 1;
            const float* src = A + (size_t)r * Kd + k0 + half * 16;
            #pragma unroll
            for (int i = 0; i < 4; i++) {
                float4 v = *(const float4*)(src + i * 4);
                const int kk = half * 16 + i * 4;
                As[(kk + 0) * ASTRIDE + m] = v.x;
                As[(kk + 1) * ASTRIDE + m] = v.y;
                As[(kk + 2) * ASTRIDE + m] = v.z;
                As[(kk + 3) * ASTRIDE + m] = v.w;
            }
        }
        // --- load B tile (32 x 64) ---
        {
            #pragma unroll
            for (int i = 0; i < 2; i++) {
                const int idx = t * 2 + i;
                const int kk  = idx >> 4;
                const int j4  = idx & 15;
                float4 v = *(const float4*)(Bm + (size_t)(k0 + kk) * Jd + j0 + j4 * 4);
                *(float4*)(&Bs[kk * BN + j4 * 4]) = v;
            }
        }
        __syncthreads();

        #pragma unroll
        for (int kk = 0; kk < BKT; kk++) {
            float4 a0 = *(const float4*)(&As[kk * ASTRIDE + trow * 8]);
            float4 a1 = *(const float4*)(&As[kk * ASTRIDE + trow * 8 + 4]);
            float4 bv = *(const float4*)(&Bs[kk * BN + tcol * 4]);
            float a[8] = {a0.x, a0.y, a0.z, a0.w, a1.x, a1.y, a1.z, a1.w};
            float b[4] = {bv.x, bv.y, bv.z, bv.w};
            #pragma unroll
            for (int i = 0; i < 8; i++)
                #pragma unroll
                for (int j = 0; j < 4; j++)
                    acc[i][j] = fmaf(a[i], b[j], acc[i][j]);
        }
        __syncthreads();
    }

    // --- epilogue: bias + optional relu, vectorized stores ---
    float4 bvec;
    {
        const int jj = j0 + tcol * 4;
        if (bias) bvec = *(const float4*)(bias + jj);
        else      bvec = make_float4(0.f, 0.f, 0.f, 0.f);
    }
    #pragma unroll
    for (int i = 0; i < 8; i++) {
        const int r = row0 + trow * 8 + i;
        if (r < Nrows) {
            float4 res;
            res.x = acc[i][0] + bvec.x;
            res.y = acc[i][1] + bvec.y;
            res.z = acc[i][2] + bvec.z;
            res.w = acc[i][3] + bvec.w;
            if (do_relu) {
                res.x = fmaxf(res.x, 0.f); res.y = fmaxf(res.y, 0.f);
                res.z = fmaxf(res.z, 0.f); res.w = fmaxf(res.w, 0.f);
            }
            *(float4*)(C + (size_t)r * Jd + j0 + tcol * 4) = res;
        }
    }
}

// ----------------------------------------------------------------------------
// Attention kernel: one warp per node.
//  Phase 1: gather 16 x-rows into per-warp smem (one pass), compute te in regs,
//           score_k = A[n] . [x_row, te] via butterfly reduce.
//  Phase 2: softmax (redundant per-lane), weighted sums -> HAGG[n] (192).
// 4 warps / 128 threads per block, 32KB static smem.
// ----------------------------------------------------------------------------
__global__ __launch_bounds__(128)
void attn_kernel(const float* __restrict__ x, const float* __restrict__ ts,
                 const int* __restrict__ idx,
                 const float* __restrict__ w0p, const float* __restrict__ b0p,
                 const float* __restrict__ Wt, const float* __restrict__ Bt,
                 const float* __restrict__ A, float* __restrict__ Hg, int N)
{
    __shared__ float xs_all[4 * KNBR * INF];   // 32 KB

    const int wid  = threadIdx.x >> 5;
    const int lane = threadIdx.x & 31;
    const int n    = blockIdx.x * 4 + wid;
    if (n >= N) return;

    float* xs = xs_all + wid * (KNBR * INF);

    // neighbor metadata in lanes 0..15
    int   m_l = 0;
    float t_l = 0.f;
    if (lane < KNBR) {
        m_l = idx[n * KNBR + lane];
        t_l = ts [n * KNBR + lane];
    }

    // A row for this node
    const float* Arow = A + (size_t)n * FD;
    const float4 aX  = *(const float4*)(Arow + lane * 4);
    const float  aT0 = Arow[INF + lane];
    const float  aT1 = Arow[INF + 32 + lane];

    // time2vec coefficients for this lane's two slots:
    //   v[lane]    : lane==0 -> linear term, else sin(t*Wt[lane-1]+Bt[lane-1])
    //   v[lane+32] : sin(t*Wt[lane+31]+Bt[lane+31])
    float w_a, b_a;
    if (lane == 0) { w_a = w0p[0]; b_a = b0p[0]; }
    else           { w_a = Wt[lane - 1]; b_a = Bt[lane - 1]; }
    const float w_b = Wt[lane + 31];
    const float b_b = Bt[lane + 31];

    float te0[KNBR], te1[KNBR], sc[KNBR];

    #pragma unroll
    for (int k = 0; k < KNBR; k++) {
        const int   m = __shfl_sync(0xffffffffu, m_l, k);
        const float t = __shfl_sync(0xffffffffu, t_l, k);
        const float4 xv = *(const float4*)(x + (size_t)m * INF + lane * 4);
        *(float4*)(xs + k * INF + lane * 4) = xv;

        float va = fmaf(t, w_a, b_a);
        if (lane != 0) va = __sinf(va);
        const float vb = __sinf(fmaf(t, w_b, b_b));
        te0[k] = va; te1[k] = vb;

        float p = xv.x * aX.x;
        p = fmaf(xv.y, aX.y, p);
        p = fmaf(xv.z, aX.z, p);
        p = fmaf(xv.w, aX.w, p);
        p = fmaf(va, aT0, p);
        p = fmaf(vb, aT1, p);
        #pragma unroll
        for (int o = 16; o > 0; o >>= 1) p += __shfl_xor_sync(0xffffffffu, p, o);
        sc[k] = p;   // scale already folded into A
    }

    // softmax (every lane redundantly)
    float mx = sc[0];
    #pragma unroll
    for (int k = 1; k < KNBR; k++) mx = fmaxf(mx, sc[k]);
    float sum = 0.f;
    #pragma unroll
    for (int k = 0; k < KNBR; k++) { sc[k] = __expf(sc[k] - mx); sum += sc[k]; }
    const float inv = 1.0f / sum;

    // weighted aggregation
    float4 acc = make_float4(0.f, 0.f, 0.f, 0.f);
    float at0 = 0.f, at1 = 0.f;
    #pragma unroll
    for (int k = 0; k < KNBR; k++) {
        const float a = sc[k] * inv;
        const float4 xv = *(const float4*)(xs + k * INF + lane * 4);
        acc.x = fmaf(a, xv.x, acc.x);
        acc.y = fmaf(a, xv.y, acc.y);
        acc.z = fmaf(a, xv.z, acc.z);
        acc.w = fmaf(a, xv.w, acc.w);
        at0 = fmaf(a, te0[k], at0);
        at1 = fmaf(a, te1[k], at1);
    }

    float* hr = Hg + (size_t)n * FD;
    *(float4*)(hr + lane * 4) = acc;
    hr[INF + lane]      = at0;
    hr[INF + 32 + lane] = at1;
}

// ----------------------------------------------------------------------------
// Launch
// Input order: x, ts, idx, t2v_w0, t2v_b0, t2v_W, t2v_B, Wq, Wk, Wv, Wo, bo
// ----------------------------------------------------------------------------
extern "C" void kernel_launch(void* const* d_in, const int* in_sizes, int n_in,
                              void* d_out, int out_size)
{
    const float* x   = (const float*)d_in[0];
    const float* ts  = (const float*)d_in[1];
    const int*   idx = (const int*)  d_in[2];
    const float* w0  = (const float*)d_in[3];
    const float* b0  = (const float*)d_in[4];
    const float* Wt  = (const float*)d_in[5];
    const float* Bt  = (const float*)d_in[6];
    const float* Wq  = (const float*)d_in[7];
    const float* Wk  = (const float*)d_in[8];
    const float* Wv  = (const float*)d_in[9];
    const float* Wo  = (const float*)d_in[10];
    const float* bo  = (const float*)d_in[11];
    float* out = (float*)d_out;

    const int N = in_sizes[0] / INF;

    void *pM, *pC, *pWvo, *pA, *pH;
    cudaGetSymbolAddress(&pM,   g_M);
    cudaGetSymbolAddress(&pC,   g_c);
    cudaGetSymbolAddress(&pWvo, g_Wvo);
    cudaGetSymbolAddress(&pA,   g_A);
    cudaGetSymbolAddress(&pH,   g_H);

    // 1) Precompute M (128x192), c (192), Wvo (192x128)
    prep_kernel<<<FD, HD>>>(Wq, Wk, Wv, Wo, w0, b0, Wt, Bt);

    // 2) A = x @ M + c        (N x 128) @ (128 x 192)
    {
        dim3 grid(FD / BN, (N + BM - 1) / BM);
        sgemm_kernel<<<grid, 256>>>(x, (const float*)pM, (const float*)pC,
                                    (float*)pA, N, INF, FD, 0);
    }

    // 3) Attention -> HAGG (N x 192)
    {
        const int blocks = (N + 3) / 4;
        attn_kernel<<<blocks, 128>>>(x, ts, idx, w0, b0, Wt, Bt,
                                     (const float*)pA, (float*)pH, N);
    }

    // 4) out = relu(HAGG @ Wvo + bo)   (N x 192) @ (192 x 128)
    {
        dim3 grid(HD / BN, (N + BM - 1) / BM);
        sgemm_kernel<<<grid, 256>>>((const float*)pH, (const float*)pWvo, bo,
                                    out, N, FD, HD, 1);
    }
}

// round 5
// speedup vs baseline: 1.0286x; 1.0286x over previous
#include <cuda_runtime.h>
#include <cstdint>

// ----------------------------------------------------------------------------
// Shapes: N=50000, K=16 neighbors, IN=128, T2V=64, F=IN+T2V=192, H=128
// Pipeline (algebraically collapsed):
//   prep  : M = (Wq1 Wk^T)/sqrt(H) [128x192], c [192], Wvo = Wv Wo [192x128]
//   gemm1 : A = x @ M + c
//   attn  : scores = A . [x_nbr, te(t)], softmax, agg -> H [N x 192]
//   gemm2 : out = relu(H @ Wvo + bo)
// GEMMs use packed fma.rn.f32x2 (2 fp32 FMA per issue slot).
// ----------------------------------------------------------------------------
#define KNBR 16
#define INF  128
#define T2VD 64
#define FD   192
#define HD   128
#define NMAX 50176

typedef unsigned long long u64;

__device__ float g_M[INF * FD];
__device__ float g_c[FD];
__device__ float g_Wvo[FD * HD];
__device__ float g_A[(size_t)NMAX * FD];
__device__ float g_H[(size_t)NMAX * FD];

// packed f32x2 helpers (base sm_100+ PTX, not 'a'-gated)
__device__ __forceinline__ u64 pack_dup(float v) {
    u64 r;
    asm("mov.b64 %0, {%1, %2};" : "=l"(r) : "f"(v), "f"(v));
    return r;
}
__device__ __forceinline__ void fma2(u64& d, u64 a, u64 b) {
    asm("fma.rn.f32x2 %0, %1, %2, %3;" : "=l"(d) : "l"(a), "l"(b), "l"(d));
}
__device__ __forceinline__ void unpack2(float& lo, float& hi, u64 v) {
    asm("mov.b64 {%0, %1}, %2;" : "=f"(lo), "=f"(hi) : "l"(v));
}

// ----------------------------------------------------------------------------
// prep: build M, c, Wvo. grid = 192 blocks (f), 128 threads (t).
// ----------------------------------------------------------------------------
__global__ void prep_kernel(const float* __restrict__ Wq, const float* __restrict__ Wk,
                            const float* __restrict__ Wv, const float* __restrict__ Wo,
                            const float* __restrict__ w0, const float* __restrict__ b0,
                            const float* __restrict__ Wt, const float* __restrict__ Bt)
{
    const int f = blockIdx.x;   // 0..191
    const int t = threadIdx.x;  // 0..127
    __shared__ float wkrow[HD];
    __shared__ float wvrow[HD];
    __shared__ float tev[T2VD];
    __shared__ float red[HD];

    wkrow[t] = Wk[f * HD + t];
    wvrow[t] = Wv[f * HD + t];
    if (t < T2VD) tev[t] = (t == 0) ? b0[0] : sinf(Bt[t - 1]);   // time2vec(0)
    __syncthreads();

    const float scale = 0.08838834764831845f;  // 1/sqrt(128)

    float m = 0.f;
    #pragma unroll 4
    for (int h = 0; h < HD; h++) m = fmaf(Wq[t * HD + h], wkrow[h], m);
    g_M[t * FD + f] = m * scale;

    float wv = 0.f;
    #pragma unroll 4
    for (int h = 0; h < HD; h++) wv = fmaf(wvrow[h], Wo[h * HD + t], wv);
    g_Wvo[f * HD + t] = wv;

    float qc = 0.f;
    #pragma unroll 4
    for (int j = 0; j < T2VD; j++) qc = fmaf(tev[j], Wq[(INF + j) * HD + t], qc);
    red[t] = qc * wkrow[t];
    __syncthreads();
    for (int s = 64; s > 0; s >>= 1) {
        if (t < s) red[t] += red[t + s];
        __syncthreads();
    }
    if (t == 0) g_c[f] = red[0] * scale;
}

// ----------------------------------------------------------------------------
// SGEMM with packed f32x2 FMAs.
// C[n,j] = act( sum_k A[n,k]*B[k,j] + bias[j] )
// BM=128, BN=64, BK=32; 256 threads (16x16); 8x4 microtile per thread,
// accumulators held as 4x4 f32x2 pairs (rows paired).
// ----------------------------------------------------------------------------
#define BM 128
#define BN 64
#define BKT 32
#define ASTRIDE 136   // 128 + 8 pad

__global__ __launch_bounds__(256, 3)
void sgemm_kernel(const float* __restrict__ A, const float* __restrict__ Bm,
                  const float* __restrict__ bias, float* __restrict__ C,
                  int Nrows, int Kd, int Jd, int do_relu)
{
    __shared__ float As[BKT * ASTRIDE];
    __shared__ float Bs[BKT * BN];

    const int t    = threadIdx.x;
    const int trow = t >> 4;   // 0..15
    const int tcol = t & 15;   // 0..15
    const int row0 = blockIdx.y * BM;
    const int j0   = blockIdx.x * BN;

    // accp[p][j] holds rows (trow*8 + 2p, +2p+1), column j0 + tcol*4 + j
    u64 accp[4][4];
    #pragma unroll
    for (int p = 0; p < 4; p++)
        #pragma unroll
        for (int j = 0; j < 4; j++) accp[p][j] = 0ull;

    for (int k0 = 0; k0 < Kd; k0 += BKT) {
        // --- load A tile (128 x 32), transposed into As[kk][m] ---
        {
            const int m    = t >> 1;
            const int half = (t & 1);
            int r = row0 + m;
            if (r >= Nrows) r = Nrows - 1;
            const float* src = A + (size_t)r * Kd + k0 + half * 16;
            #pragma unroll
            for (int i = 0; i < 4; i++) {
                float4 v = *(const float4*)(src + i * 4);
                const int kk = half * 16 + i * 4;
                As[(kk + 0) * ASTRIDE + m] = v.x;
                As[(kk + 1) * ASTRIDE + m] = v.y;
                As[(kk + 2) * ASTRIDE + m] = v.z;
                As[(kk + 3) * ASTRIDE + m] = v.w;
            }
        }
        // --- load B tile (32 x 64) ---
        {
            #pragma unroll
            for (int i = 0; i < 2; i++) {
                const int idx = t * 2 + i;
                const int kk  = idx >> 4;
                const int j4  = idx & 15;
                float4 v = *(const float4*)(Bm + (size_t)(k0 + kk) * Jd + j0 + j4 * 4);
                *(float4*)(&Bs[kk * BN + j4 * 4]) = v;
            }
        }
        __syncthreads();

        #pragma unroll
        for (int kk = 0; kk < BKT; kk++) {
            // a: 8 consecutive rows -> 4 packed pairs (aligned 16B loads)
            const u64* ap = (const u64*)(&As[kk * ASTRIDE + trow * 8]);
            u64 a0 = ap[0], a1 = ap[1], a2 = ap[2], a3 = ap[3];
            // b: 4 scalars, duplicated into both packed halves
            float4 bv = *(const float4*)(&Bs[kk * BN + tcol * 4]);
            u64 b0 = pack_dup(bv.x);
            u64 b1 = pack_dup(bv.y);
            u64 b2 = pack_dup(bv.z);
            u64 b3 = pack_dup(bv.w);

            fma2(accp[0][0], a0, b0); fma2(accp[0][1], a0, b1);
            fma2(accp[0][2], a0, b2); fma2(accp[0][3], a0, b3);
            fma2(accp[1][0], a1, b0); fma2(accp[1][1], a1, b1);
            fma2(accp[1][2], a1, b2); fma2(accp[1][3], a1, b3);
            fma2(accp[2][0], a2, b0); fma2(accp[2][1], a2, b1);
            fma2(accp[2][2], a2, b2); fma2(accp[2][3], a2, b3);
            fma2(accp[3][0], a3, b0); fma2(accp[3][1], a3, b1);
            fma2(accp[3][2], a3, b2); fma2(accp[3][3], a3, b3);
        }
        __syncthreads();
    }

    // --- epilogue: unpack, bias + optional relu, vectorized stores ---
    float4 bvec = *(const float4*)(bias + j0 + tcol * 4);
    #pragma unroll
    for (int p = 0; p < 4; p++) {
        float lo[4], hi[4];
        #pragma unroll
        for (int j = 0; j < 4; j++) unpack2(lo[j], hi[j], accp[p][j]);

        const int r0 = row0 + trow * 8 + 2 * p;
        if (r0 < Nrows) {
            float4 res;
            res.x = lo[0] + bvec.x; res.y = lo[1] + bvec.y;
            res.z = lo[2] + bvec.z; res.w = lo[3] + bvec.w;
            if (do_relu) {
                res.x = fmaxf(res.x, 0.f); res.y = fmaxf(res.y, 0.f);
                res.z = fmaxf(res.z, 0.f); res.w = fmaxf(res.w, 0.f);
            }
            *(float4*)(C + (size_t)r0 * Jd + j0 + tcol * 4) = res;
        }
        if (r0 + 1 < Nrows) {
            float4 res;
            res.x = hi[0] + bvec.x; res.y = hi[1] + bvec.y;
            res.z = hi[2] + bvec.z; res.w = hi[3] + bvec.w;
            if (do_relu) {
                res.x = fmaxf(res.x, 0.f); res.y = fmaxf(res.y, 0.f);
                res.z = fmaxf(res.z, 0.f); res.w = fmaxf(res.w, 0.f);
            }
            *(float4*)(C + (size_t)(r0 + 1) * Jd + j0 + tcol * 4) = res;
        }
    }
}

// ----------------------------------------------------------------------------
// Attention kernel: one warp per node (unchanged from passing R3 version).
// ----------------------------------------------------------------------------
__global__ __launch_bounds__(128)
void attn_kernel(const float* __restrict__ x, const float* __restrict__ ts,
                 const int* __restrict__ idx,
                 const float* __restrict__ w0p, const float* __restrict__ b0p,
                 const float* __restrict__ Wt, const float* __restrict__ Bt,
                 const float* __restrict__ A, float* __restrict__ Hg, int N)
{
    __shared__ float xs_all[4 * KNBR * INF];   // 32 KB

    const int wid  = threadIdx.x >> 5;
    const int lane = threadIdx.x & 31;
    const int n    = blockIdx.x * 4 + wid;
    if (n >= N) return;

    float* xs = xs_all + wid * (KNBR * INF);

    int   m_l = 0;
    float t_l = 0.f;
    if (lane < KNBR) {
        m_l = idx[n * KNBR + lane];
        t_l = ts [n * KNBR + lane];
    }

    const float* Arow = A + (size_t)n * FD;
    const float4 aX  = *(const float4*)(Arow + lane * 4);
    const float  aT0 = Arow[INF + lane];
    const float  aT1 = Arow[INF + 32 + lane];

    float w_a, b_a;
    if (lane == 0) { w_a = w0p[0]; b_a = b0p[0]; }
    else           { w_a = Wt[lane - 1]; b_a = Bt[lane - 1]; }
    const float w_b = Wt[lane + 31];
    const float b_b = Bt[lane + 31];

    float te0[KNBR], te1[KNBR], sc[KNBR];

    #pragma unroll
    for (int k = 0; k < KNBR; k++) {
        const int   m = __shfl_sync(0xffffffffu, m_l, k);
        const float t = __shfl_sync(0xffffffffu, t_l, k);
        const float4 xv = *(const float4*)(x + (size_t)m * INF + lane * 4);
        *(float4*)(xs + k * INF + lane * 4) = xv;

        float va = fmaf(t, w_a, b_a);
        if (lane != 0) va = __sinf(va);
        const float vb = __sinf(fmaf(t, w_b, b_b));
        te0[k] = va; te1[k] = vb;

        float p = xv.x * aX.x;
        p = fmaf(xv.y, aX.y, p);
        p = fmaf(xv.z, aX.z, p);
        p = fmaf(xv.w, aX.w, p);
        p = fmaf(va, aT0, p);
        p = fmaf(vb, aT1, p);
        #pragma unroll
        for (int o = 16; o > 0; o >>= 1) p += __shfl_xor_sync(0xffffffffu, p, o);
        sc[k] = p;
    }

    float mx = sc[0];
    #pragma unroll
    for (int k = 1; k < KNBR; k++) mx = fmaxf(mx, sc[k]);
    float sum = 0.f;
    #pragma unroll
    for (int k = 0; k < KNBR; k++) { sc[k] = __expf(sc[k] - mx); sum += sc[k]; }
    const float inv = 1.0f / sum;

    float4 acc = make_float4(0.f, 0.f, 0.f, 0.f);
    float at0 = 0.f, at1 = 0.f;
    #pragma unroll
    for (int k = 0; k < KNBR; k++) {
        const float a = sc[k] * inv;
        const float4 xv = *(const float4*)(xs + k * INF + lane * 4);
        acc.x = fmaf(a, xv.x, acc.x);
        acc.y = fmaf(a, xv.y, acc.y);
        acc.z = fmaf(a, xv.z, acc.z);
        acc.w = fmaf(a, xv.w, acc.w);
        at0 = fmaf(a, te0[k], at0);
        at1 = fmaf(a, te1[k], at1);
    }

    float* hr = Hg + (size_t)n * FD;
    *(float4*)(hr + lane * 4) = acc;
    hr[INF + lane]      = at0;
    hr[INF + 32 + lane] = at1;
}

// ----------------------------------------------------------------------------
// Launch. Input order: x, ts, idx, t2v_w0, t2v_b0, t2v_W, t2v_B, Wq, Wk, Wv, Wo, bo
// ----------------------------------------------------------------------------
extern "C" void kernel_launch(void* const* d_in, const int* in_sizes, int n_in,
                              void* d_out, int out_size)
{
    const float* x   = (const float*)d_in[0];
    const float* ts  = (const float*)d_in[1];
    const int*   idx = (const int*)  d_in[2];
    const float* w0  = (const float*)d_in[3];
    const float* b0  = (const float*)d_in[4];
    const float* Wt  = (const float*)d_in[5];
    const float* Bt  = (const float*)d_in[6];
    const float* Wq  = (const float*)d_in[7];
    const float* Wk  = (const float*)d_in[8];
    const float* Wv  = (const float*)d_in[9];
    const float* Wo  = (const float*)d_in[10];
    const float* bo  = (const float*)d_in[11];
    float* out = (float*)d_out;

    const int N = in_sizes[0] / INF;

    void *pM, *pC, *pWvo, *pA, *pH;
    cudaGetSymbolAddress(&pM,   g_M);
    cudaGetSymbolAddress(&pC,   g_c);
    cudaGetSymbolAddress(&pWvo, g_Wvo);
    cudaGetSymbolAddress(&pA,   g_A);
    cudaGetSymbolAddress(&pH,   g_H);

    // 1) Precompute M (128x192), c (192), Wvo (192x128)
    prep_kernel<<<FD, HD>>>(Wq, Wk, Wv, Wo, w0, b0, Wt, Bt);

    // 2) A = x @ M + c        (N x 128) @ (128 x 192)
    {
        dim3 grid(FD / BN, (N + BM - 1) / BM);
        sgemm_kernel<<<grid, 256>>>(x, (const float*)pM, (const float*)pC,
                                    (float*)pA, N, INF, FD, 0);
    }

    // 3) Attention -> HAGG (N x 192)
    attn_kernel<<<(N + 3) / 4, 128>>>(x, ts, idx, w0, b0, Wt, Bt,
                                      (const float*)pA, (float*)pH, N);

    // 4) out = relu(HAGG @ Wvo + bo)   (N x 192) @ (192 x 128)
    {
        dim3 grid(HD / BN, (N + BM - 1) / BM);
        sgemm_kernel<<<grid, 256>>>((const float*)pH, (const float*)pWvo, bo,
                                    out, N, FD, HD, 1);
    }
}

// round 6
// speedup vs baseline: 1.1910x; 1.1578x over previous
#include <cuda_runtime.h>
#include <cuda_bf16.h>
#include <cstdint>

// ----------------------------------------------------------------------------
// Shapes: N=50000, K=16 neighbors, IN=128, T2V=64, F=IN+T2V=192, H=128
// Pipeline (algebraically collapsed):
//   prep  : M = (Wq1 Wk^T)/sqrt(H), c, Wvo = Wv Wo -> bf16 hi/lo B^T images
//   gemm1 : A = x @ M + c              (mma.sync bf16 2-split, 3 terms)
//   attn  : scores/softmax/agg -> H
//   gemm2 : out = relu(H @ Wvo + bo)   (mma.sync bf16 2-split)
// ----------------------------------------------------------------------------
#define KNBR 16
#define INF  128
#define T2VD 64
#define FD   192
#define HD   128
#define NMAX 50176

__device__ float g_c[FD];
__device__ __align__(16) float g_A[(size_t)NMAX * FD];
__device__ __align__(16) float g_H[(size_t)NMAX * FD];
// weight products, pre-split bf16, stored B^T row-major [j][k]
__device__ __align__(16) __nv_bfloat16 g_B1hi[FD * INF];   // j<192, k<128
__device__ __align__(16) __nv_bfloat16 g_B1lo[FD * INF];
__device__ __align__(16) __nv_bfloat16 g_B2hi[HD * FD];    // j<128, k<192
__device__ __align__(16) __nv_bfloat16 g_B2lo[HD * FD];

// ============================ helpers =======================================
__device__ __forceinline__ uint32_t smem_u32(const void* p) {
    uint32_t a;
    asm("{ .reg .u64 t; cvta.to.shared.u64 t, %1; cvt.u32.u64 %0, t; }"
        : "=r"(a) : "l"(p));
    return a;
}
// pack two floats -> bf16x2 (lo in low half, hi in high half)
__device__ __forceinline__ uint32_t bf2pack(float lo, float hi) {
    uint32_t r;
    asm("cvt.rn.bf16x2.f32 %0, %1, %2;" : "=r"(r) : "f"(hi), "f"(lo));
    return r;
}
// split pair (v0,v1) into bf16 hi-pair and lo-pair (residual)
__device__ __forceinline__ void split2(float v0, float v1, uint32_t& hp, uint32_t& lp) {
    hp = bf2pack(v0, v1);
    float h0 = __uint_as_float(hp << 16);
    float h1 = __uint_as_float(hp & 0xFFFF0000u);
    lp = bf2pack(v0 - h0, v1 - h1);
}
#define LDSM4(r, addr) \
    asm volatile("ldmatrix.sync.aligned.m8n8.x4.shared.b16 {%0,%1,%2,%3}, [%4];" \
        : "=r"((r)[0]), "=r"((r)[1]), "=r"((r)[2]), "=r"((r)[3]) : "r"(addr))
#define MMA_BF16(d, a, b0_, b1_) \
    asm volatile("mma.sync.aligned.m16n8k16.row.col.f32.bf16.bf16.f32 " \
        "{%0,%1,%2,%3}, {%4,%5,%6,%7}, {%8,%9}, {%0,%1,%2,%3};" \
        : "+f"((d)[0]), "+f"((d)[1]), "+f"((d)[2]), "+f"((d)[3]) \
        : "r"((a)[0]), "r"((a)[1]), "r"((a)[2]), "r"((a)[3]), "r"(b0_), "r"(b1_))

// ============================ prep ==========================================
// grid=192 (f), block=128 (t). Emits bf16 hi/lo B^T images + fp32 bias c.
__global__ void prep_kernel(const float* __restrict__ Wq, const float* __restrict__ Wk,
                            const float* __restrict__ Wv, const float* __restrict__ Wo,
                            const float* __restrict__ w0, const float* __restrict__ b0,
                            const float* __restrict__ Wt, const float* __restrict__ Bt)
{
    const int f = blockIdx.x;   // 0..191
    const int t = threadIdx.x;  // 0..127
    __shared__ float wkrow[HD];
    __shared__ float wvrow[HD];
    __shared__ float tev[T2VD];
    __shared__ float red[HD];

    wkrow[t] = Wk[f * HD + t];
    wvrow[t] = Wv[f * HD + t];
    if (t < T2VD) tev[t] = (t == 0) ? b0[0] : sinf(Bt[t - 1]);   // time2vec(0)
    __syncthreads();

    const float scale = 0.08838834764831845f;  // 1/sqrt(128)

    // M[t][f] = scale * dot(Wq[t,:], Wk[f,:])  -> B1[j=f][k=t]
    float m = 0.f;
    #pragma unroll 4
    for (int h = 0; h < HD; h++) m = fmaf(Wq[t * HD + h], wkrow[h], m);
    m *= scale;
    {
        __nv_bfloat16 hi = __float2bfloat16(m);
        __nv_bfloat16 lo = __float2bfloat16(m - __bfloat162float(hi));
        g_B1hi[f * INF + t] = hi;
        g_B1lo[f * INF + t] = lo;
    }

    // Wvo[f][t] = dot(Wv[f,:], Wo[:,t])        -> B2[j=t][k=f]
    float wv = 0.f;
    #pragma unroll 4
    for (int h = 0; h < HD; h++) wv = fmaf(wvrow[h], Wo[h * HD + t], wv);
    {
        __nv_bfloat16 hi = __float2bfloat16(wv);
        __nv_bfloat16 lo = __float2bfloat16(wv - __bfloat162float(hi));
        g_B2hi[t * FD + f] = hi;
        g_B2lo[t * FD + f] = lo;
    }

    // c[f]
    float qc = 0.f;
    #pragma unroll 4
    for (int j = 0; j < T2VD; j++) qc = fmaf(tev[j], Wq[(INF + j) * HD + t], qc);
    red[t] = qc * wkrow[t];
    __syncthreads();
    for (int s = 64; s > 0; s >>= 1) {
        if (t < s) red[t] += red[t + s];
        __syncthreads();
    }
    if (t == 0) g_c[f] = red[0] * scale;
}

// ============================ HMMA GEMM =====================================
// C[n, 0..JD) = act( sum_k A[n,k] * B[j,k] + bias[j] )
// A: fp32 row-major [*,KD] (split to bf16 hi/lo during smem load)
// B: bf16 hi/lo, B^T row-major [j][KD]
// CTA tile 128 x 64, whole K in smem, 8 warps (each 32x32), 3 MMA terms.
template<int KD, int JD, int RELU>
__global__ __launch_bounds__(256, 1)
void mma_gemm(const float* __restrict__ A,
              const __nv_bfloat16* __restrict__ Bhi, const __nv_bfloat16* __restrict__ Blo,
              const float* __restrict__ bias, float* __restrict__ C, int Nrows)
{
    constexpr int AG     = KD / 8;            // 16B granules per row
    constexpr int ABYTES = 128 * KD * 2;      // one A buffer (hi or lo)
    constexpr int BBYTES = 64 * KD * 2;       // one B buffer

    extern __shared__ __align__(16) char smem[];
    char* cA_hi = smem;
    char* cA_lo = smem + ABYTES;
    char* cB_hi = smem + 2 * ABYTES;
    char* cB_lo = cB_hi + BBYTES;
    const uint32_t sA_hi = smem_u32(smem);
    const uint32_t sB_hi = sA_hi + 2 * ABYTES;

    const int tid  = threadIdx.x;
    const int row0 = blockIdx.y * 128;
    const int j0   = blockIdx.x * 64;

    // ---- A tile: load fp32, split -> bf16 hi/lo, swizzled granules ----
    for (int c = tid; c < 128 * AG; c += 256) {
        const int r = c / AG, g = c % AG;
        int sr = row0 + r; if (sr >= Nrows) sr = Nrows - 1;
        const float4* s = (const float4*)(A + (size_t)sr * KD + g * 8);
        const float4 v0 = s[0], v1 = s[1];
        uint32_t h0, l0, h1, l1, h2, l2, h3, l3;
        split2(v0.x, v0.y, h0, l0); split2(v0.z, v0.w, h1, l1);
        split2(v1.x, v1.y, h2, l2); split2(v1.z, v1.w, h3, l3);
        const uint32_t off = (uint32_t)((r * AG + (g ^ (r & 7))) * 16);
        *(uint4*)(cA_hi + off) = make_uint4(h0, h1, h2, h3);
        *(uint4*)(cA_lo + off) = make_uint4(l0, l1, l2, l3);
    }
    // ---- B tile: straight 16B copies of pre-split bf16, swizzled ----
    for (int c = tid; c < 64 * AG; c += 256) {
        const int r = c / AG, g = c % AG;
        const uint32_t off = (uint32_t)((r * AG + (g ^ (r & 7))) * 16);
        *(uint4*)(cB_hi + off) = *(const uint4*)(Bhi + (size_t)(j0 + r) * KD + g * 8);
        *(uint4*)(cB_lo + off) = *(const uint4*)(Blo + (size_t)(j0 + r) * KD + g * 8);
    }
    __syncthreads();

    const int lane = tid & 31;
    const int wid  = tid >> 5;
    const int wm   = wid & 3;    // 0..3 -> rows wm*32
    const int wn   = wid >> 2;   // 0..1 -> cols wn*32

    // A ldmatrix addressing (x4: lanes 0-15 rows, lane>>4 selects k-granule)
    uint32_t aRowOff[2]; uint32_t aSw[2];
    #pragma unroll
    for (int mt = 0; mt < 2; mt++) {
        const int r = wm * 32 + mt * 16 + (lane & 15);
        aRowOff[mt] = (uint32_t)(r * (AG * 16));
        aSw[mt] = (uint32_t)(r & 7);
    }
    const uint32_t aDg = (uint32_t)(lane >> 4);
    // B ldmatrix addressing (x4 -> two n8 fragments)
    uint32_t bRowOff[2]; uint32_t bSw[2];
    #pragma unroll
    for (int np = 0; np < 2; np++) {
        const int r = wn * 32 + np * 16 + (lane & 7) + ((lane >> 4) << 3);
        bRowOff[np] = (uint32_t)(r * (AG * 16));
        bSw[np] = (uint32_t)(r & 7);
    }
    const uint32_t bDg = (uint32_t)((lane >> 3) & 1);

    float acc[2][4][4];
    #pragma unroll
    for (int mt = 0; mt < 2; mt++)
        #pragma unroll
        for (int nt = 0; nt < 4; nt++)
            #pragma unroll
            for (int q = 0; q < 4; q++) acc[mt][nt][q] = 0.f;

    #pragma unroll
    for (int ks = 0; ks < KD / 16; ks++) {
        const uint32_t kg = 2 * ks;
        uint32_t ah[2][4], al[2][4], bh[2][4], bl[2][4];
        #pragma unroll
        for (int mt = 0; mt < 2; mt++) {
            const uint32_t addr = sA_hi + aRowOff[mt] + ((kg + aDg) ^ aSw[mt]) * 16u;
            LDSM4(ah[mt], addr);
            LDSM4(al[mt], addr + (uint32_t)ABYTES);
        }
        #pragma unroll
        for (int np = 0; np < 2; np++) {
            const uint32_t addr = sB_hi + bRowOff[np] + ((kg + bDg) ^ bSw[np]) * 16u;
            LDSM4(bh[np], addr);
            LDSM4(bl[np], addr + (uint32_t)BBYTES);
        }
        #pragma unroll
        for (int mt = 0; mt < 2; mt++)
            #pragma unroll
            for (int np = 0; np < 2; np++)
                #pragma unroll
                for (int h = 0; h < 2; h++) {
                    float* d = acc[mt][np * 2 + h];
                    MMA_BF16(d, ah[mt], bh[np][2 * h], bh[np][2 * h + 1]);
                    MMA_BF16(d, al[mt], bh[np][2 * h], bh[np][2 * h + 1]);
                    MMA_BF16(d, ah[mt], bl[np][2 * h], bl[np][2 * h + 1]);
                }
    }

    // ---- epilogue: bias + optional relu ----
    const int g  = lane >> 2;
    const int tg = lane & 3;
    #pragma unroll
    for (int nt = 0; nt < 4; nt++) {
        const int col = j0 + wn * 32 + nt * 8 + tg * 2;
        const float b0 = bias[col], b1 = bias[col + 1];
        #pragma unroll
        for (int mt = 0; mt < 2; mt++) {
            const float* d = acc[mt][nt];
            const int r0 = row0 + wm * 32 + mt * 16 + g;
            if (r0 < Nrows) {
                float2 v = make_float2(d[0] + b0, d[1] + b1);
                if (RELU) { v.x = fmaxf(v.x, 0.f); v.y = fmaxf(v.y, 0.f); }
                *(float2*)(C + (size_t)r0 * JD + col) = v;
            }
            const int r1 = r0 + 8;
            if (r1 < Nrows) {
                float2 v = make_float2(d[2] + b0, d[3] + b1);
                if (RELU) { v.x = fmaxf(v.x, 0.f); v.y = fmaxf(v.y, 0.f); }
                *(float2*)(C + (size_t)r1 * JD + col) = v;
            }
        }
    }
}

// ============================ attention =====================================
__global__ __launch_bounds__(128)
void attn_kernel(const float* __restrict__ x, const float* __restrict__ ts,
                 const int* __restrict__ idx,
                 const float* __restrict__ w0p, const float* __restrict__ b0p,
                 const float* __restrict__ Wt, const float* __restrict__ Bt,
                 const float* __restrict__ A, float* __restrict__ Hg, int N)
{
    __shared__ float xs_all[4 * KNBR * INF];   // 32 KB

    const int wid  = threadIdx.x >> 5;
    const int lane = threadIdx.x & 31;
    const int n    = blockIdx.x * 4 + wid;
    if (n >= N) return;

    float* xs = xs_all + wid * (KNBR * INF);

    int   m_l = 0;
    float t_l = 0.f;
    if (lane < KNBR) {
        m_l = idx[n * KNBR + lane];
        t_l = ts [n * KNBR + lane];
    }

    const float* Arow = A + (size_t)n * FD;
    const float4 aX  = *(const float4*)(Arow + lane * 4);
    const float  aT0 = Arow[INF + lane];
    const float  aT1 = Arow[INF + 32 + lane];

    float w_a, b_a;
    if (lane == 0) { w_a = w0p[0]; b_a = b0p[0]; }
    else           { w_a = Wt[lane - 1]; b_a = Bt[lane - 1]; }
    const float w_b = Wt[lane + 31];
    const float b_b = Bt[lane + 31];

    float te0[KNBR], te1[KNBR], sc[KNBR];

    #pragma unroll
    for (int k = 0; k < KNBR; k++) {
        const int   m = __shfl_sync(0xffffffffu, m_l, k);
        const float t = __shfl_sync(0xffffffffu, t_l, k);
        const float4 xv = *(const float4*)(x + (size_t)m * INF + lane * 4);
        *(float4*)(xs + k * INF + lane * 4) = xv;

        float va = fmaf(t, w_a, b_a);
        if (lane != 0) va = __sinf(va);
        const float vb = __sinf(fmaf(t, w_b, b_b));
        te0[k] = va; te1[k] = vb;

        float p = xv.x * aX.x;
        p = fmaf(xv.y, aX.y, p);
        p = fmaf(xv.z, aX.z, p);
        p = fmaf(xv.w, aX.w, p);
        p = fmaf(va, aT0, p);
        p = fmaf(vb, aT1, p);
        #pragma unroll
        for (int o = 16; o > 0; o >>= 1) p += __shfl_xor_sync(0xffffffffu, p, o);
        sc[k] = p;
    }

    float mx = sc[0];
    #pragma unroll
    for (int k = 1; k < KNBR; k++) mx = fmaxf(mx, sc[k]);
    float sum = 0.f;
    #pragma unroll
    for (int k = 0; k < KNBR; k++) { sc[k] = __expf(sc[k] - mx); sum += sc[k]; }
    const float inv = 1.0f / sum;

    float4 acc = make_float4(0.f, 0.f, 0.f, 0.f);
    float at0 = 0.f, at1 = 0.f;
    #pragma unroll
    for (int k = 0; k < KNBR; k++) {
        const float a = sc[k] * inv;
        const float4 xv = *(const float4*)(xs + k * INF + lane * 4);
        acc.x = fmaf(a, xv.x, acc.x);
        acc.y = fmaf(a, xv.y, acc.y);
        acc.z = fmaf(a, xv.z, acc.z);
        acc.w = fmaf(a, xv.w, acc.w);
        at0 = fmaf(a, te0[k], at0);
        at1 = fmaf(a, te1[k], at1);
    }

    float* hr = Hg + (size_t)n * FD;
    *(float4*)(hr + lane * 4) = acc;
    hr[INF + lane]      = at0;
    hr[INF + 32 + lane] = at1;
}

// ============================ launch ========================================
// Input order: x, ts, idx, t2v_w0, t2v_b0, t2v_W, t2v_B, Wq, Wk, Wv, Wo, bo
extern "C" void kernel_launch(void* const* d_in, const int* in_sizes, int n_in,
                              void* d_out, int out_size)
{
    const float* x   = (const float*)d_in[0];
    const float* ts  = (const float*)d_in[1];
    const int*   idx = (const int*)  d_in[2];
    const float* w0  = (const float*)d_in[3];
    const float* b0  = (const float*)d_in[4];
    const float* Wt  = (const float*)d_in[5];
    const float* Bt  = (const float*)d_in[6];
    const float* Wq  = (const float*)d_in[7];
    const float* Wk  = (const float*)d_in[8];
    const float* Wv  = (const float*)d_in[9];
    const float* Wo  = (const float*)d_in[10];
    const float* bo  = (const float*)d_in[11];
    float* out = (float*)d_out;

    const int N     = in_sizes[0] / INF;
    const int tiles = (N + 127) / 128;

    void *pC, *pA, *pH, *pB1h, *pB1l, *pB2h, *pB2l;
    cudaGetSymbolAddress(&pC,   g_c);
    cudaGetSymbolAddress(&pA,   g_A);
    cudaGetSymbolAddress(&pH,   g_H);
    cudaGetSymbolAddress(&pB1h, g_B1hi);
    cudaGetSymbolAddress(&pB1l, g_B1lo);
    cudaGetSymbolAddress(&pB2h, g_B2hi);
    cudaGetSymbolAddress(&pB2l, g_B2lo);

    const int SMEM1 = 2 * (128 * 128 * 2) + 2 * (64 * 128 * 2);   //  98304
    const int SMEM2 = 2 * (128 * 192 * 2) + 2 * (64 * 192 * 2);   // 147456
    cudaFuncSetAttribute(mma_gemm<128, 192, 0>,
                         cudaFuncAttributeMaxDynamicSharedMemorySize, SMEM1);
    cudaFuncSetAttribute(mma_gemm<192, 128, 1>,
                         cudaFuncAttributeMaxDynamicSharedMemorySize, SMEM2);

    // 1) prep: weight products + bf16 hi/lo B^T images + bias c
    prep_kernel<<<FD, HD>>>(Wq, Wk, Wv, Wo, w0, b0, Wt, Bt);

    // 2) A = x @ M + c        (128->192, HMMA)
    {
        dim3 grid(FD / 64, tiles);
        mma_gemm<128, 192, 0><<<grid, 256, SMEM1>>>(
            x, (const __nv_bfloat16*)pB1h, (const __nv_bfloat16*)pB1l,
            (const float*)pC, (float*)pA, N);
    }

    // 3) attention -> H
    attn_kernel<<<(N + 3) / 4, 128>>>(x, ts, idx, w0, b0, Wt, Bt,
                                      (const float*)pA, (float*)pH, N);

    // 4) out = relu(H @ Wvo + bo)   (192->128, HMMA)
    {
        dim3 grid(HD / 64, tiles);
        mma_gemm<192, 128, 1><<<grid, 256, SMEM2>>>(
            (const float*)pH, (const __nv_bfloat16*)pB2h, (const __nv_bfloat16*)pB2l,
            bo, out, N);
    }
}

// round 7
// speedup vs baseline: 1.5061x; 1.2646x over previous
#include <cuda_runtime.h>
#include <cuda_bf16.h>
#include <cstdint>

// ----------------------------------------------------------------------------
// Shapes: N=50000, K=16 neighbors, IN=128, T2V=64, F=IN+T2V=192, H=128
// Pipeline (algebraically collapsed):
//   prep  : M = (Wq1 Wk^T)/sqrt(H), c, Wvo = Wv Wo -> bf16 hi/lo B^T images
//   gemm1 : A = x @ M + c              (mma.sync bf16 2-split, 3 terms)
//   attn  : scores/softmax/agg -> H
//   gemm2 : out = relu(H @ Wvo + bo)   (mma.sync bf16 2-split)
// GEMMs: K-chunked (BK=64) double-buffered smem pipeline, 2 CTAs/SM.
// ----------------------------------------------------------------------------
#define KNBR 16
#define INF  128
#define T2VD 64
#define FD   192
#define HD   128
#define NMAX 50176

__device__ float g_c[FD];
__device__ __align__(16) float g_A[(size_t)NMAX * FD];
__device__ __align__(16) float g_H[(size_t)NMAX * FD];
// weight products, pre-split bf16, stored B^T row-major [j][k]
__device__ __align__(16) __nv_bfloat16 g_B1hi[FD * INF];   // j<192, k<128
__device__ __align__(16) __nv_bfloat16 g_B1lo[FD * INF];
__device__ __align__(16) __nv_bfloat16 g_B2hi[HD * FD];    // j<128, k<192
__device__ __align__(16) __nv_bfloat16 g_B2lo[HD * FD];

// ============================ helpers =======================================
__device__ __forceinline__ uint32_t smem_u32(const void* p) {
    uint32_t a;
    asm("{ .reg .u64 t; cvta.to.shared.u64 t, %1; cvt.u32.u64 %0, t; }"
        : "=r"(a) : "l"(p));
    return a;
}
__device__ __forceinline__ uint32_t bf2pack(float lo, float hi) {
    uint32_t r;
    asm("cvt.rn.bf16x2.f32 %0, %1, %2;" : "=r"(r) : "f"(hi), "f"(lo));
    return r;
}
__device__ __forceinline__ void split2(float v0, float v1, uint32_t& hp, uint32_t& lp) {
    hp = bf2pack(v0, v1);
    float h0 = __uint_as_float(hp << 16);
    float h1 = __uint_as_float(hp & 0xFFFF0000u);
    lp = bf2pack(v0 - h0, v1 - h1);
}
#define LDSM4(r, addr) \
    asm volatile("ldmatrix.sync.aligned.m8n8.x4.shared.b16 {%0,%1,%2,%3}, [%4];" \
        : "=r"((r)[0]), "=r"((r)[1]), "=r"((r)[2]), "=r"((r)[3]) : "r"(addr))
#define MMA_BF16(d, a, b0_, b1_) \
    asm volatile("mma.sync.aligned.m16n8k16.row.col.f32.bf16.bf16.f32 " \
        "{%0,%1,%2,%3}, {%4,%5,%6,%7}, {%8,%9}, {%0,%1,%2,%3};" \
        : "+f"((d)[0]), "+f"((d)[1]), "+f"((d)[2]), "+f"((d)[3]) \
        : "r"((a)[0]), "r"((a)[1]), "r"((a)[2]), "r"((a)[3]), "r"(b0_), "r"(b1_))

// ============================ prep ==========================================
__global__ void prep_kernel(const float* __restrict__ Wq, const float* __restrict__ Wk,
                            const float* __restrict__ Wv, const float* __restrict__ Wo,
                            const float* __restrict__ w0, const float* __restrict__ b0,
                            const float* __restrict__ Wt, const float* __restrict__ Bt)
{
    const int f = blockIdx.x;   // 0..191
    const int t = threadIdx.x;  // 0..127
    __shared__ float wkrow[HD];
    __shared__ float wvrow[HD];
    __shared__ float tev[T2VD];
    __shared__ float red[HD];

    wkrow[t] = Wk[f * HD + t];
    wvrow[t] = Wv[f * HD + t];
    if (t < T2VD) tev[t] = (t == 0) ? b0[0] : sinf(Bt[t - 1]);   // time2vec(0)
    __syncthreads();

    const float scale = 0.08838834764831845f;  // 1/sqrt(128)

    // M[t][f] -> B1[j=f][k=t]
    float m = 0.f;
    #pragma unroll 4
    for (int h = 0; h < HD; h++) m = fmaf(Wq[t * HD + h], wkrow[h], m);
    m *= scale;
    {
        __nv_bfloat16 hi = __float2bfloat16(m);
        __nv_bfloat16 lo = __float2bfloat16(m - __bfloat162float(hi));
        g_B1hi[f * INF + t] = hi;
        g_B1lo[f * INF + t] = lo;
    }

    // Wvo[f][t] -> B2[j=t][k=f]
    float wv = 0.f;
    #pragma unroll 4
    for (int h = 0; h < HD; h++) wv = fmaf(wvrow[h], Wo[h * HD + t], wv);
    {
        __nv_bfloat16 hi = __float2bfloat16(wv);
        __nv_bfloat16 lo = __float2bfloat16(wv - __bfloat162float(hi));
        g_B2hi[t * FD + f] = hi;
        g_B2lo[t * FD + f] = lo;
    }

    // c[f]
    float qc = 0.f;
    #pragma unroll 4
    for (int j = 0; j < T2VD; j++) qc = fmaf(tev[j], Wq[(INF + j) * HD + t], qc);
    red[t] = qc * wkrow[t];
    __syncthreads();
    for (int s = 64; s > 0; s >>= 1) {
        if (t < s) red[t] += red[t + s];
        __syncthreads();
    }
    if (t == 0) g_c[f] = red[0] * scale;
}

// ============================ HMMA GEMM (pipelined) =========================
// C[n, 0..JD) = act( sum_k A[n,k] * B[j,k] + bias[j] )
// CTA tile 128 x 64, BK=64 chunks, 2-stage double buffer, 8 warps (32x32 each).
template<int KD, int JD, int RELU>
__global__ __launch_bounds__(256, 2)
void mma_gemm(const float* __restrict__ A,
              const __nv_bfloat16* __restrict__ Bhi, const __nv_bfloat16* __restrict__ Blo,
              const float* __restrict__ bias, float* __restrict__ C, int Nrows)
{
    constexpr int BK     = 64;
    constexpr int NC     = KD / BK;
    constexpr int ABYTES = 128 * BK * 2;              // 16384 (one of hi/lo)
    constexpr int BBYTES = 64 * BK * 2;               //  8192
    constexpr int STAGE  = 2 * ABYTES + 2 * BBYTES;   // 49152

    extern __shared__ __align__(16) char smem[];
    const uint32_t sbase = smem_u32(smem);

    const int tid  = threadIdx.x;
    const int row0 = blockIdx.y * 128;
    const int j0   = blockIdx.x * 64;

    // chunk c -> stage s (LDG -> split -> STS, swizzled granules)
    auto load_chunk = [&](int c, int s) {
        char* dA_hi = smem + s * STAGE;
        char* dA_lo = dA_hi + ABYTES;
        char* dB_hi = dA_hi + 2 * ABYTES;
        char* dB_lo = dB_hi + BBYTES;
        const int kbase = c * BK;
        // A: 128 rows x 8 granules (16B bf16x8), 4 tasks/thread
        #pragma unroll
        for (int it = 0; it < 4; it++) {
            const int task = tid + it * 256;          // 0..1023
            const int r = task >> 3, g = task & 7;
            int sr = row0 + r; if (sr >= Nrows) sr = Nrows - 1;
            const float4* src = (const float4*)(A + (size_t)sr * KD + kbase + g * 8);
            const float4 v0 = src[0], v1 = src[1];
            uint32_t h0, l0, h1, l1, h2, l2, h3, l3;
            split2(v0.x, v0.y, h0, l0); split2(v0.z, v0.w, h1, l1);
            split2(v1.x, v1.y, h2, l2); split2(v1.z, v1.w, h3, l3);
            const uint32_t off = (uint32_t)((r * 8 + (g ^ (r & 7))) * 16);
            *(uint4*)(dA_hi + off) = make_uint4(h0, h1, h2, h3);
            *(uint4*)(dA_lo + off) = make_uint4(l0, l1, l2, l3);
        }
        // B: 64 rows x 8 granules, 2 tasks/thread (pre-split bf16, plain copy)
        #pragma unroll
        for (int it = 0; it < 2; it++) {
            const int task = tid + it * 256;          // 0..511
            const int r = task >> 3, g = task & 7;
            const uint32_t off = (uint32_t)((r * 8 + (g ^ (r & 7))) * 16);
            const size_t gi = (size_t)(j0 + r) * KD + kbase + g * 8;
            *(uint4*)(dB_hi + off) = *(const uint4*)(Bhi + gi);
            *(uint4*)(dB_lo + off) = *(const uint4*)(Blo + gi);
        }
    };

    const int lane = tid & 31;
    const int wid  = tid >> 5;
    const int wm   = wid & 3;    // rows wm*32
    const int wn   = wid >> 2;   // cols wn*32
    const uint32_t sw  = (uint32_t)(lane & 7);        // granule swizzle (r&7)
    const uint32_t aDg = (uint32_t)(lane >> 4);
    const uint32_t bDg = (uint32_t)((lane >> 3) & 1);

    uint32_t aOff[2], bOff[2];   // stage-relative row byte offsets
    #pragma unroll
    for (int mt = 0; mt < 2; mt++)
        aOff[mt] = (uint32_t)((wm * 32 + mt * 16 + (lane & 15)) * 128);
    #pragma unroll
    for (int np = 0; np < 2; np++)
        bOff[np] = (uint32_t)((wn * 32 + np * 16 + (lane & 7) + ((lane >> 4) << 3)) * 128);

    float acc[2][4][4];
    #pragma unroll
    for (int mt = 0; mt < 2; mt++)
        #pragma unroll
        for (int nt = 0; nt < 4; nt++)
            #pragma unroll
            for (int q = 0; q < 4; q++) acc[mt][nt][q] = 0.f;

    load_chunk(0, 0);
    __syncthreads();

    #pragma unroll
    for (int c = 0; c < NC; c++) {
        if (c + 1 < NC) load_chunk(c + 1, (c + 1) & 1);

        const uint32_t sA = sbase + (uint32_t)((c & 1) * STAGE);
        const uint32_t sB = sA + 2 * ABYTES;
        #pragma unroll
        for (int ks = 0; ks < BK / 16; ks++) {
            const uint32_t kg = 2 * ks;
            uint32_t ah[2][4], al[2][4], bh[2][4], bl[2][4];
            #pragma unroll
            for (int mt = 0; mt < 2; mt++) {
                const uint32_t addr = sA + aOff[mt] + ((kg + aDg) ^ sw) * 16u;
                LDSM4(ah[mt], addr);
                LDSM4(al[mt], addr + (uint32_t)ABYTES);
            }
            #pragma unroll
            for (int np = 0; np < 2; np++) {
                const uint32_t addr = sB + bOff[np] + ((kg + bDg) ^ sw) * 16u;
                LDSM4(bh[np], addr);
                LDSM4(bl[np], addr + (uint32_t)BBYTES);
            }
            #pragma unroll
            for (int mt = 0; mt < 2; mt++)
                #pragma unroll
                for (int np = 0; np < 2; np++)
                    #pragma unroll
                    for (int h = 0; h < 2; h++) {
                        float* d = acc[mt][np * 2 + h];
                        MMA_BF16(d, ah[mt], bh[np][2 * h], bh[np][2 * h + 1]);
                        MMA_BF16(d, al[mt], bh[np][2 * h], bh[np][2 * h + 1]);
                        MMA_BF16(d, ah[mt], bl[np][2 * h], bl[np][2 * h + 1]);
                    }
        }
        __syncthreads();
    }

    // ---- epilogue: bias + optional relu ----
    const int g  = lane >> 2;
    const int tg = lane & 3;
    #pragma unroll
    for (int nt = 0; nt < 4; nt++) {
        const int col = j0 + wn * 32 + nt * 8 + tg * 2;
        const float b0 = bias[col], b1 = bias[col + 1];
        #pragma unroll
        for (int mt = 0; mt < 2; mt++) {
            const float* d = acc[mt][nt];
            const int r0 = row0 + wm * 32 + mt * 16 + g;
            if (r0 < Nrows) {
                float2 v = make_float2(d[0] + b0, d[1] + b1);
                if (RELU) { v.x = fmaxf(v.x, 0.f); v.y = fmaxf(v.y, 0.f); }
                *(float2*)(C + (size_t)r0 * JD + col) = v;
            }
            const int r1 = r0 + 8;
            if (r1 < Nrows) {
                float2 v = make_float2(d[2] + b0, d[3] + b1);
                if (RELU) { v.x = fmaxf(v.x, 0.f); v.y = fmaxf(v.y, 0.f); }
                *(float2*)(C + (size_t)(r1) * JD + col) = v;
            }
        }
    }
}

// ============================ attention =====================================
__global__ __launch_bounds__(128)
void attn_kernel(const float* __restrict__ x, const float* __restrict__ ts,
                 const int* __restrict__ idx,
                 const float* __restrict__ w0p, const float* __restrict__ b0p,
                 const float* __restrict__ Wt, const float* __restrict__ Bt,
                 const float* __restrict__ A, float* __restrict__ Hg, int N)
{
    __shared__ float xs_all[4 * KNBR * INF];   // 32 KB

    const int wid  = threadIdx.x >> 5;
    const int lane = threadIdx.x & 31;
    const int n    = blockIdx.x * 4 + wid;
    if (n >= N) return;

    float* xs = xs_all + wid * (KNBR * INF);

    int   m_l = 0;
    float t_l = 0.f;
    if (lane < KNBR) {
        m_l = idx[n * KNBR + lane];
        t_l = ts [n * KNBR + lane];
    }

    const float* Arow = A + (size_t)n * FD;
    const float4 aX  = *(const float4*)(Arow + lane * 4);
    const float  aT0 = Arow[INF + lane];
    const float  aT1 = Arow[INF + 32 + lane];

    float w_a, b_a;
    if (lane == 0) { w_a = w0p[0]; b_a = b0p[0]; }
    else           { w_a = Wt[lane - 1]; b_a = Bt[lane - 1]; }
    const float w_b = Wt[lane + 31];
    const float b_b = Bt[lane + 31];

    float te0[KNBR], te1[KNBR], sc[KNBR];

    #pragma unroll
    for (int k = 0; k < KNBR; k++) {
        const int   m = __shfl_sync(0xffffffffu, m_l, k);
        const float t = __shfl_sync(0xffffffffu, t_l, k);
        const float4 xv = *(const float4*)(x + (size_t)m * INF + lane * 4);
        *(float4*)(xs + k * INF + lane * 4) = xv;

        float va = fmaf(t, w_a, b_a);
        if (lane != 0) va = __sinf(va);
        const float vb = __sinf(fmaf(t, w_b, b_b));
        te0[k] = va; te1[k] = vb;

        float p = xv.x * aX.x;
        p = fmaf(xv.y, aX.y, p);
        p = fmaf(xv.z, aX.z, p);
        p = fmaf(xv.w, aX.w, p);
        p = fmaf(va, aT0, p);
        p = fmaf(vb, aT1, p);
        #pragma unroll
        for (int o = 16; o > 0; o >>= 1) p += __shfl_xor_sync(0xffffffffu, p, o);
        sc[k] = p;
    }

    float mx = sc[0];
    #pragma unroll
    for (int k = 1; k < KNBR; k++) mx = fmaxf(mx, sc[k]);
    float sum = 0.f;
    #pragma unroll
    for (int k = 0; k < KNBR; k++) { sc[k] = __expf(sc[k] - mx); sum += sc[k]; }
    const float inv = 1.0f / sum;

    float4 acc = make_float4(0.f, 0.f, 0.f, 0.f);
    float at0 = 0.f, at1 = 0.f;
    #pragma unroll
    for (int k = 0; k < KNBR; k++) {
        const float a = sc[k] * inv;
        const float4 xv = *(const float4*)(xs + k * INF + lane * 4);
        acc.x = fmaf(a, xv.x, acc.x);
        acc.y = fmaf(a, xv.y, acc.y);
        acc.z = fmaf(a, xv.z, acc.z);
        acc.w = fmaf(a, xv.w, acc.w);
        at0 = fmaf(a, te0[k], at0);
        at1 = fmaf(a, te1[k], at1);
    }

    float* hr = Hg + (size_t)n * FD;
    *(float4*)(hr + lane * 4) = acc;
    hr[INF + lane]      = at0;
    hr[INF + 32 + lane] = at1;
}

// ============================ launch ========================================
// Input order: x, ts, idx, t2v_w0, t2v_b0, t2v_W, t2v_B, Wq, Wk, Wv, Wo, bo
extern "C" void kernel_launch(void* const* d_in, const int* in_sizes, int n_in,
                              void* d_out, int out_size)
{
    const float* x   = (const float*)d_in[0];
    const float* ts  = (const float*)d_in[1];
    const int*   idx = (const int*)  d_in[2];
    const float* w0  = (const float*)d_in[3];
    const float* b0  = (const float*)d_in[4];
    const float* Wt  = (const float*)d_in[5];
    const float* Bt  = (const float*)d_in[6];
    const float* Wq  = (const float*)d_in[7];
    const float* Wk  = (const float*)d_in[8];
    const float* Wv  = (const float*)d_in[9];
    const float* Wo  = (const float*)d_in[10];
    const float* bo  = (const float*)d_in[11];
    float* out = (float*)d_out;

    const int N     = in_sizes[0] / INF;
    const int tiles = (N + 127) / 128;

    void *pC, *pA, *pH, *pB1h, *pB1l, *pB2h, *pB2l;
    cudaGetSymbolAddress(&pC,   g_c);
    cudaGetSymbolAddress(&pA,   g_A);
    cudaGetSymbolAddress(&pH,   g_H);
    cudaGetSymbolAddress(&pB1h, g_B1hi);
    cudaGetSymbolAddress(&pB1l, g_B1lo);
    cudaGetSymbolAddress(&pB2h, g_B2hi);
    cudaGetSymbolAddress(&pB2l, g_B2lo);

    const int SMEM = 2 * (2 * (128 * 64 * 2) + 2 * (64 * 64 * 2));   // 98304
    cudaFuncSetAttribute(mma_gemm<128, 192, 0>,
                         cudaFuncAttributeMaxDynamicSharedMemorySize, SMEM);
    cudaFuncSetAttribute(mma_gemm<192, 128, 1>,
                         cudaFuncAttributeMaxDynamicSharedMemorySize, SMEM);

    // 1) prep: weight products + bf16 hi/lo B^T images + bias c
    prep_kernel<<<FD, HD>>>(Wq, Wk, Wv, Wo, w0, b0, Wt, Bt);

    // 2) A = x @ M + c        (128->192, HMMA pipelined)
    {
        dim3 grid(FD / 64, tiles);
        mma_gemm<128, 192, 0><<<grid, 256, SMEM>>>(
            x, (const __nv_bfloat16*)pB1h, (const __nv_bfloat16*)pB1l,
            (const float*)pC, (float*)pA, N);
    }

    // 3) attention -> H
    attn_kernel<<<(N + 3) / 4, 128>>>(x, ts, idx, w0, b0, Wt, Bt,
                                      (const float*)pA, (float*)pH, N);

    // 4) out = relu(H @ Wvo + bo)   (192->128, HMMA pipelined)
    {
        dim3 grid(HD / 64, tiles);
        mma_gemm<192, 128, 1><<<grid, 256, SMEM>>>(
            (const float*)pH, (const __nv_bfloat16*)pB2h, (const __nv_bfloat16*)pB2l,
            bo, out, N);
    }
}